// round 8
// baseline (speedup 1.0000x reference)
#include <cuda_runtime.h>
#include <cstdint>

// ZGate (qudit diagonal phase): D=4, S=1, INDEX=(0,2,5,8), L=10, B=16.
// phase(n) = i^p, p = ((n>>18)+(n>>14)+(n>>8)+(n>>2)) & 3.
// Output (verified) = REAL part only, [N, B] float32:
//   p=0 -> +re   p=1 -> -im   p=2 -> -re   p=3 -> +im
// One thread = one row (B=16 floats = 4 float4): p computed ONCE per thread,
// single plane-select pointer, 4 consecutive float4 loads (MLP=4).

__global__ __launch_bounds__(256) void zgate_row_kernel(
    const float4* __restrict__ xre,   // real plane, plane/4 float4
    const float4* __restrict__ xim,   // imag plane
    float4* __restrict__ out,         // [N, B] float32 as float4
    long long nrows)                  // N
{
    const long long t = (long long)blockIdx.x * blockDim.x + threadIdx.x;
    if (t >= nrows) return;

    const unsigned n = (unsigned)t;
    const unsigned p = ((n >> 18) + (n >> 14) + (n >> 8) + (n >> 2)) & 3u;

    const float4* __restrict__ src = (p & 1u) ? xim : xre;
    const float sign = (p == 1u || p == 2u) ? -1.0f : 1.0f;

    const long long base = t << 2;  // 4 float4 per row

    float4 v0 = src[base + 0];
    float4 v1 = src[base + 1];
    float4 v2 = src[base + 2];
    float4 v3 = src[base + 3];

    v0.x *= sign; v0.y *= sign; v0.z *= sign; v0.w *= sign;
    v1.x *= sign; v1.y *= sign; v1.z *= sign; v1.w *= sign;
    v2.x *= sign; v2.y *= sign; v2.z *= sign; v2.w *= sign;
    v3.x *= sign; v3.y *= sign; v3.z *= sign; v3.w *= sign;

    out[base + 0] = v0;
    out[base + 1] = v1;
    out[base + 2] = v2;
    out[base + 3] = v3;
}

// ---- fallbacks for other output layouts (defensive, unchanged) ----

__device__ __forceinline__ void phase_cs(unsigned n, float& c, float& s) {
    const unsigned p = ((n >> 18) + (n >> 14) + (n >> 8) + (n >> 2)) & 3u;
    c = (float)((p == 0u) - (p == 2u));
    s = (float)((p == 1u) - (p == 3u));
}

__global__ __launch_bounds__(256) void zgate_planar_kernel(
    const float4* __restrict__ xre, const float4* __restrict__ xim,
    float4* __restrict__ outre, float4* __restrict__ outim, long long total4)
{
    const long long t = (long long)blockIdx.x * blockDim.x + threadIdx.x;
    if (t >= total4) return;
    const unsigned n = (unsigned)(t >> 2);
    float c, s; phase_cs(n, c, s);
    const float4 re = xre[t], im = xim[t];
    float4 oR, oI;
    oR.x = c * re.x - s * im.x;  oI.x = s * re.x + c * im.x;
    oR.y = c * re.y - s * im.y;  oI.y = s * re.y + c * im.y;
    oR.z = c * re.z - s * im.z;  oI.z = s * re.z + c * im.z;
    oR.w = c * re.w - s * im.w;  oI.w = s * re.w + c * im.w;
    outre[t] = oR;
    outim[t] = oI;
}

__global__ __launch_bounds__(256) void zgate_safe_kernel(
    const float* __restrict__ x, float* __restrict__ out,
    long long plane, long long out_floats)
{
    const long long e = (long long)blockIdx.x * blockDim.x + threadIdx.x;
    if (e >= plane) return;
    const unsigned n = (unsigned)(e >> 4);
    float c, s; phase_cs(n, c, s);
    const float re = x[e], im = x[plane + e];
    const long long o = 2 * e;
    if (o < out_floats)     out[o]     = c * re - s * im;
    if (o + 1 < out_floats) out[o + 1] = s * re + c * im;
}

extern "C" void kernel_launch(void* const* d_in, const int* in_sizes, int n_in,
                              void* d_out, int out_size) {
    const float* x = (const float*)d_in[0];             // [2, N, B]
    const long long plane = (long long)in_sizes[0] / 2; // N*B floats per plane

    const float4* xre = (const float4*)x;
    const float4* xim = (const float4*)(x + plane);

    const int threads = 256;

    if ((long long)out_size == plane) {
        const long long nrows = plane / 16;   // B = 16 floats per row
        const int blocks = (int)((nrows + threads - 1) / threads);
        zgate_row_kernel<<<blocks, threads>>>(xre, xim, (float4*)d_out, nrows);
    } else if ((long long)out_size == 2 * plane) {
        float* out = (float*)d_out;
        const long long total4 = plane / 4;
        const int blocks = (int)((total4 + threads - 1) / threads);
        zgate_planar_kernel<<<blocks, threads>>>(
            xre, xim, (float4*)out, (float4*)(out + plane), total4);
    } else {
        const int blocks = (int)((plane + threads - 1) / threads);
        zgate_safe_kernel<<<blocks, threads>>>(x, (float*)d_out, plane,
                                               (long long)out_size);
    }
}

// round 9
// speedup vs baseline: 1.3653x; 1.3653x over previous
#include <cuda_runtime.h>
#include <cstdint>

// ZGate (qudit diagonal phase): D=4, S=1, INDEX=(0,2,5,8), L=10, B=16.
// phase(n) = i^p. For float4 index i (n = i>>2, 4 float4 per row of B=16):
//   p = ((i>>20)+(i>>16)+(i>>10)+(i>>4)) & 3
// Output (verified) = REAL part only, [N, B] float32:
//   p=0 -> +re   p=1 -> -im   p=2 -> -re   p=3 -> +im
// Round-6 winning layout (lanes consecutive, k block-strided, MLP=4),
// slimmed: 32-bit indices, sign via XOR of the float sign bit, no guards
// (grid exactly covers total4; harness sizes are multiples of 1024 float4).

constexpr int VPT = 4;   // float4 per thread, block-strided

__global__ __launch_bounds__(256) void zgate_fast_kernel(
    const uint4* __restrict__ xre,
    const uint4* __restrict__ xim,
    uint4* __restrict__ out)
{
    const unsigned base = blockIdx.x * (256u * VPT) + threadIdx.x;

    unsigned idx[VPT];
    const uint4* __restrict__ src[VPT];
    unsigned m[VPT];
    uint4 v[VPT];

#pragma unroll
    for (int k = 0; k < VPT; k++) {
        const unsigned i = base + k * 256u;
        idx[k] = i;
        const unsigned p = ((i >> 20) + (i >> 16) + (i >> 10) + (i >> 4)) & 3u;
        src[k] = (p & 1u) ? xim : xre;
        // negate for p==1 or p==2:  (p==1)|(p==2)  <=>  p+1 has bit1 set? p in {1,2}
        m[k] = (p == 1u || p == 2u) ? 0x80000000u : 0u;
    }
#pragma unroll
    for (int k = 0; k < VPT; k++) v[k] = src[k][idx[k]];
#pragma unroll
    for (int k = 0; k < VPT; k++) {
        uint4 o;
        o.x = v[k].x ^ m[k];
        o.y = v[k].y ^ m[k];
        o.z = v[k].z ^ m[k];
        o.w = v[k].w ^ m[k];
        out[idx[k]] = o;
    }
}

// Guarded variant for sizes not a multiple of 1024 float4.
__global__ __launch_bounds__(256) void zgate_fast_guard_kernel(
    const uint4* __restrict__ xre,
    const uint4* __restrict__ xim,
    uint4* __restrict__ out, unsigned total4)
{
    const unsigned base = blockIdx.x * (256u * VPT) + threadIdx.x;
#pragma unroll
    for (int k = 0; k < VPT; k++) {
        const unsigned i = base + k * 256u;
        if (i >= total4) continue;
        const unsigned p = ((i >> 20) + (i >> 16) + (i >> 10) + (i >> 4)) & 3u;
        const uint4* __restrict__ src = (p & 1u) ? xim : xre;
        const unsigned m = (p == 1u || p == 2u) ? 0x80000000u : 0u;
        uint4 v = src[i];
        v.x ^= m; v.y ^= m; v.z ^= m; v.w ^= m;
        out[i] = v;
    }
}

// ---- fallbacks for other output layouts (defensive, unchanged) ----

__device__ __forceinline__ void phase_cs(unsigned n, float& c, float& s) {
    const unsigned p = ((n >> 18) + (n >> 14) + (n >> 8) + (n >> 2)) & 3u;
    c = (float)((p == 0u) - (p == 2u));
    s = (float)((p == 1u) - (p == 3u));
}

__global__ __launch_bounds__(256) void zgate_planar_kernel(
    const float4* __restrict__ xre, const float4* __restrict__ xim,
    float4* __restrict__ outre, float4* __restrict__ outim, long long total4)
{
    const long long t = (long long)blockIdx.x * blockDim.x + threadIdx.x;
    if (t >= total4) return;
    const unsigned n = (unsigned)(t >> 2);
    float c, s; phase_cs(n, c, s);
    const float4 re = xre[t], im = xim[t];
    float4 oR, oI;
    oR.x = c * re.x - s * im.x;  oI.x = s * re.x + c * im.x;
    oR.y = c * re.y - s * im.y;  oI.y = s * re.y + c * im.y;
    oR.z = c * re.z - s * im.z;  oI.z = s * re.z + c * im.z;
    oR.w = c * re.w - s * im.w;  oI.w = s * re.w + c * im.w;
    outre[t] = oR;
    outim[t] = oI;
}

__global__ __launch_bounds__(256) void zgate_safe_kernel(
    const float* __restrict__ x, float* __restrict__ out,
    long long plane, long long out_floats)
{
    const long long e = (long long)blockIdx.x * blockDim.x + threadIdx.x;
    if (e >= plane) return;
    const unsigned n = (unsigned)(e >> 4);
    float c, s; phase_cs(n, c, s);
    const float re = x[e], im = x[plane + e];
    const long long o = 2 * e;
    if (o < out_floats)     out[o]     = c * re - s * im;
    if (o + 1 < out_floats) out[o + 1] = s * re + c * im;
}

extern "C" void kernel_launch(void* const* d_in, const int* in_sizes, int n_in,
                              void* d_out, int out_size) {
    const float* x = (const float*)d_in[0];             // [2, N, B]
    const long long plane = (long long)in_sizes[0] / 2; // N*B floats per plane

    const int threads = 256;

    if ((long long)out_size == plane) {
        const long long total4 = plane / 4;
        const long long per_block = (long long)threads * VPT;  // 1024
        if (total4 % per_block == 0 && total4 < (1LL << 31)) {
            const int blocks = (int)(total4 / per_block);
            zgate_fast_kernel<<<blocks, threads>>>(
                (const uint4*)x, (const uint4*)(x + plane), (uint4*)d_out);
        } else {
            const int blocks = (int)((total4 + per_block - 1) / per_block);
            zgate_fast_guard_kernel<<<blocks, threads>>>(
                (const uint4*)x, (const uint4*)(x + plane), (uint4*)d_out,
                (unsigned)total4);
        }
    } else if ((long long)out_size == 2 * plane) {
        float* out = (float*)d_out;
        const long long total4 = plane / 4;
        const int blocks = (int)((total4 + threads - 1) / threads);
        zgate_planar_kernel<<<blocks, threads>>>(
            (const float4*)x, (const float4*)(x + plane),
            (float4*)out, (float4*)(out + plane), total4);
    } else {
        const int blocks = (int)((plane + threads - 1) / threads);
        zgate_safe_kernel<<<blocks, threads>>>(x, (float*)d_out, plane,
                                               (long long)out_size);
    }
}

// round 10
// speedup vs baseline: 1.3695x; 1.0031x over previous
#include <cuda_runtime.h>
#include <cstdint>

// ZGate (qudit diagonal phase): D=4, S=1, INDEX=(0,2,5,8), L=10, B=16.
// phase(n) = i^p. For float4 index i (n = i>>2):
//   p = ((i>>20)+(i>>16)+(i>>10)+(i>>4)) & 3
// Output (verified) = REAL part only, [N, B] float32:
//   p=0 -> +re   p=1 -> -im   p=2 -> -re   p=3 -> +im
// Round-8 layout (lanes consecutive, k block-strided, MLP=4, XOR sign) +
// L2 residency management: __ldcg loads (L2-cache, no L1 alloc, input stays
// resident across graph replays) and __stcs stores (evict-first streaming,
// output never displaces the input read set in L2).

constexpr int VPT = 4;   // float4 per thread, block-strided

__global__ __launch_bounds__(256) void zgate_fast_kernel(
    const uint4* __restrict__ xre,
    const uint4* __restrict__ xim,
    uint4* __restrict__ out)
{
    const unsigned base = blockIdx.x * (256u * VPT) + threadIdx.x;

    unsigned idx[VPT];
    const uint4* src[VPT];
    unsigned m[VPT];
    uint4 v[VPT];

#pragma unroll
    for (int k = 0; k < VPT; k++) {
        const unsigned i = base + k * 256u;
        idx[k] = i;
        const unsigned p = ((i >> 20) + (i >> 16) + (i >> 10) + (i >> 4)) & 3u;
        src[k] = (p & 1u) ? xim : xre;
        m[k] = (p == 1u || p == 2u) ? 0x80000000u : 0u;
    }
#pragma unroll
    for (int k = 0; k < VPT; k++) v[k] = __ldcg(src[k] + idx[k]);
#pragma unroll
    for (int k = 0; k < VPT; k++) {
        uint4 o;
        o.x = v[k].x ^ m[k];
        o.y = v[k].y ^ m[k];
        o.z = v[k].z ^ m[k];
        o.w = v[k].w ^ m[k];
        __stcs(out + idx[k], o);
    }
}

// Guarded variant for sizes not a multiple of 1024 float4.
__global__ __launch_bounds__(256) void zgate_fast_guard_kernel(
    const uint4* __restrict__ xre,
    const uint4* __restrict__ xim,
    uint4* __restrict__ out, unsigned total4)
{
    const unsigned base = blockIdx.x * (256u * VPT) + threadIdx.x;
#pragma unroll
    for (int k = 0; k < VPT; k++) {
        const unsigned i = base + k * 256u;
        if (i >= total4) continue;
        const unsigned p = ((i >> 20) + (i >> 16) + (i >> 10) + (i >> 4)) & 3u;
        const uint4* src = (p & 1u) ? xim : xre;
        const unsigned m = (p == 1u || p == 2u) ? 0x80000000u : 0u;
        uint4 v = __ldcg(src + i);
        v.x ^= m; v.y ^= m; v.z ^= m; v.w ^= m;
        __stcs(out + i, v);
    }
}

// ---- fallbacks for other output layouts (defensive, unchanged) ----

__device__ __forceinline__ void phase_cs(unsigned n, float& c, float& s) {
    const unsigned p = ((n >> 18) + (n >> 14) + (n >> 8) + (n >> 2)) & 3u;
    c = (float)((p == 0u) - (p == 2u));
    s = (float)((p == 1u) - (p == 3u));
}

__global__ __launch_bounds__(256) void zgate_planar_kernel(
    const float4* __restrict__ xre, const float4* __restrict__ xim,
    float4* __restrict__ outre, float4* __restrict__ outim, long long total4)
{
    const long long t = (long long)blockIdx.x * blockDim.x + threadIdx.x;
    if (t >= total4) return;
    const unsigned n = (unsigned)(t >> 2);
    float c, s; phase_cs(n, c, s);
    const float4 re = xre[t], im = xim[t];
    float4 oR, oI;
    oR.x = c * re.x - s * im.x;  oI.x = s * re.x + c * im.x;
    oR.y = c * re.y - s * im.y;  oI.y = s * re.y + c * im.y;
    oR.z = c * re.z - s * im.z;  oI.z = s * re.z + c * im.z;
    oR.w = c * re.w - s * im.w;  oI.w = s * re.w + c * im.w;
    outre[t] = oR;
    outim[t] = oI;
}

__global__ __launch_bounds__(256) void zgate_safe_kernel(
    const float* __restrict__ x, float* __restrict__ out,
    long long plane, long long out_floats)
{
    const long long e = (long long)blockIdx.x * blockDim.x + threadIdx.x;
    if (e >= plane) return;
    const unsigned n = (unsigned)(e >> 4);
    float c, s; phase_cs(n, c, s);
    const float re = x[e], im = x[plane + e];
    const long long o = 2 * e;
    if (o < out_floats)     out[o]     = c * re - s * im;
    if (o + 1 < out_floats) out[o + 1] = s * re + c * im;
}

extern "C" void kernel_launch(void* const* d_in, const int* in_sizes, int n_in,
                              void* d_out, int out_size) {
    const float* x = (const float*)d_in[0];             // [2, N, B]
    const long long plane = (long long)in_sizes[0] / 2; // N*B floats per plane

    const int threads = 256;

    if ((long long)out_size == plane) {
        const long long total4 = plane / 4;
        const long long per_block = (long long)threads * VPT;  // 1024
        if (total4 % per_block == 0 && total4 < (1LL << 31)) {
            const int blocks = (int)(total4 / per_block);
            zgate_fast_kernel<<<blocks, threads>>>(
                (const uint4*)x, (const uint4*)(x + plane), (uint4*)d_out);
        } else {
            const int blocks = (int)((total4 + per_block - 1) / per_block);
            zgate_fast_guard_kernel<<<blocks, threads>>>(
                (const uint4*)x, (const uint4*)(x + plane), (uint4*)d_out,
                (unsigned)total4);
        }
    } else if ((long long)out_size == 2 * plane) {
        float* out = (float*)d_out;
        const long long total4 = plane / 4;
        const int blocks = (int)((total4 + threads - 1) / threads);
        zgate_planar_kernel<<<blocks, threads>>>(
            (const float4*)x, (const float4*)(x + plane),
            (float4*)out, (float4*)(out + plane), total4);
    } else {
        const int blocks = (int)((plane + threads - 1) / threads);
        zgate_safe_kernel<<<blocks, threads>>>(x, (float*)d_out, plane,
                                               (long long)out_size);
    }
}

// round 11
// speedup vs baseline: 1.4975x; 1.0935x over previous
#include <cuda_runtime.h>
#include <cstdint>

// ZGate (qudit diagonal phase): D=4, S=1, INDEX=(0,2,5,8), L=10, B=16.
// phase(n) = i^p. For float4 index i (n = i>>2):
//   p = ((i>>20)+(i>>16)+(i>>10)+(i>>4)) & 3
// Output (verified) = REAL part only, [N, B] float32:
//   p=0 -> +re   p=1 -> -im   p=2 -> -re   p=3 -> +im
// Persistent-grid version: exactly 8 blocks per SM resident (one wave, no
// wave transitions), each block loops over 1024-uint4 tiles with the proven
// pattern: consecutive lanes, k block-strided (MLP=4), XOR sign, ldcg/stcs.

constexpr int VPT = 4;            // uint4 per thread per tile
constexpr int THREADS = 256;
constexpr unsigned TILE = THREADS * VPT;   // 1024 uint4 per tile

__global__ __launch_bounds__(THREADS) void zgate_persist_kernel(
    const uint4* __restrict__ xre,
    const uint4* __restrict__ xim,
    uint4* __restrict__ out,
    unsigned total4)              // multiple of TILE in this path
{
    const unsigned tile_stride = gridDim.x * TILE;

    for (unsigned t0 = blockIdx.x * TILE + threadIdx.x; t0 < total4;
         t0 += tile_stride) {

        unsigned idx[VPT];
        const uint4* src[VPT];
        unsigned m[VPT];
        uint4 v[VPT];

#pragma unroll
        for (int k = 0; k < VPT; k++) {
            const unsigned i = t0 + k * (unsigned)THREADS;
            idx[k] = i;
            const unsigned p =
                ((i >> 20) + (i >> 16) + (i >> 10) + (i >> 4)) & 3u;
            src[k] = (p & 1u) ? xim : xre;
            m[k] = (p == 1u || p == 2u) ? 0x80000000u : 0u;
        }
#pragma unroll
        for (int k = 0; k < VPT; k++) v[k] = __ldcg(src[k] + idx[k]);
#pragma unroll
        for (int k = 0; k < VPT; k++) {
            uint4 o;
            o.x = v[k].x ^ m[k];
            o.y = v[k].y ^ m[k];
            o.z = v[k].z ^ m[k];
            o.w = v[k].w ^ m[k];
            __stcs(out + idx[k], o);
        }
    }
}

// Guarded single-pass variant for sizes not a multiple of TILE.
__global__ __launch_bounds__(THREADS) void zgate_fast_guard_kernel(
    const uint4* __restrict__ xre,
    const uint4* __restrict__ xim,
    uint4* __restrict__ out, unsigned total4)
{
    const unsigned base = blockIdx.x * TILE + threadIdx.x;
#pragma unroll
    for (int k = 0; k < VPT; k++) {
        const unsigned i = base + k * (unsigned)THREADS;
        if (i >= total4) continue;
        const unsigned p = ((i >> 20) + (i >> 16) + (i >> 10) + (i >> 4)) & 3u;
        const uint4* src = (p & 1u) ? xim : xre;
        const unsigned m = (p == 1u || p == 2u) ? 0x80000000u : 0u;
        uint4 v = __ldcg(src + i);
        v.x ^= m; v.y ^= m; v.z ^= m; v.w ^= m;
        __stcs(out + i, v);
    }
}

// ---- fallbacks for other output layouts (defensive, unchanged) ----

__device__ __forceinline__ void phase_cs(unsigned n, float& c, float& s) {
    const unsigned p = ((n >> 18) + (n >> 14) + (n >> 8) + (n >> 2)) & 3u;
    c = (float)((p == 0u) - (p == 2u));
    s = (float)((p == 1u) - (p == 3u));
}

__global__ __launch_bounds__(256) void zgate_planar_kernel(
    const float4* __restrict__ xre, const float4* __restrict__ xim,
    float4* __restrict__ outre, float4* __restrict__ outim, long long total4)
{
    const long long t = (long long)blockIdx.x * blockDim.x + threadIdx.x;
    if (t >= total4) return;
    const unsigned n = (unsigned)(t >> 2);
    float c, s; phase_cs(n, c, s);
    const float4 re = xre[t], im = xim[t];
    float4 oR, oI;
    oR.x = c * re.x - s * im.x;  oI.x = s * re.x + c * im.x;
    oR.y = c * re.y - s * im.y;  oI.y = s * re.y + c * im.y;
    oR.z = c * re.z - s * im.z;  oI.z = s * re.z + c * im.z;
    oR.w = c * re.w - s * im.w;  oI.w = s * re.w + c * im.w;
    outre[t] = oR;
    outim[t] = oI;
}

__global__ __launch_bounds__(256) void zgate_safe_kernel(
    const float* __restrict__ x, float* __restrict__ out,
    long long plane, long long out_floats)
{
    const long long e = (long long)blockIdx.x * blockDim.x + threadIdx.x;
    if (e >= plane) return;
    const unsigned n = (unsigned)(e >> 4);
    float c, s; phase_cs(n, c, s);
    const float re = x[e], im = x[plane + e];
    const long long o = 2 * e;
    if (o < out_floats)     out[o]     = c * re - s * im;
    if (o + 1 < out_floats) out[o + 1] = s * re + c * im;
}

extern "C" void kernel_launch(void* const* d_in, const int* in_sizes, int n_in,
                              void* d_out, int out_size) {
    const float* x = (const float*)d_in[0];             // [2, N, B]
    const long long plane = (long long)in_sizes[0] / 2; // N*B floats per plane

    if ((long long)out_size == plane) {
        const long long total4 = plane / 4;
        if (total4 % TILE == 0 && total4 < (1LL << 31)) {
            // One resident wave: 148 SMs x 8 blocks.
            const unsigned ntiles = (unsigned)(total4 / TILE);
            unsigned blocks = 148u * 8u;
            if (blocks > ntiles) blocks = ntiles;
            zgate_persist_kernel<<<blocks, THREADS>>>(
                (const uint4*)x, (const uint4*)(x + plane), (uint4*)d_out,
                (unsigned)total4);
        } else {
            const long long per_block = TILE;
            const int blocks = (int)((total4 + per_block - 1) / per_block);
            zgate_fast_guard_kernel<<<blocks, THREADS>>>(
                (const uint4*)x, (const uint4*)(x + plane), (uint4*)d_out,
                (unsigned)total4);
        }
    } else if ((long long)out_size == 2 * plane) {
        float* out = (float*)d_out;
        const long long total4 = plane / 4;
        const int blocks = (int)((total4 + 255) / 256);
        zgate_planar_kernel<<<blocks, 256>>>(
            (const float4*)x, (const float4*)(x + plane),
            (float4*)out, (float4*)(out + plane), total4);
    } else {
        const int blocks = (int)((plane + 255) / 256);
        zgate_safe_kernel<<<blocks, 256>>>(x, (float*)d_out, plane,
                                           (long long)out_size);
    }
}